// round 9
// baseline (speedup 1.0000x reference)
#include <cuda_runtime.h>
#include <cuda_fp16.h>
#include <cstdint>

// Problem constants
#define NUM_AUTHOR 16604
#define NUM_NODES  29059
#define DIM        300
#define NB         32768
#define NE         1048576

// GEMM shape: proj = emb[29059,300] @ Wcat[960,300]^T  (padded M=29184, K=320)
#define MPAD  29184        // 228 * 128
#define KA    320          // padded K for wcat rows
#define NPADC 960          // 3 sections x 320 cols
#define PSTR  960          // proj row stride (halves)

// Scratch (device globals; allocation-free rule)
__device__ float  g_wcat[(size_t)NPADC * KA];    // tf32-rounded, remapped W1
__device__ __half g_proj[(size_t)MPAD * PSTR];   // projected table, fp16 (56 MB)
__device__ float  g_rsB[DIM];                    // rowsum of Wb (empty-type-1 fallback)
__device__ float  g_rsC[DIM];                    // rowsum of Wc (empty-type-2 fallback)
__device__ int    g_off[NB + 1];

__device__ __forceinline__ float tf32r(float x) {
    uint32_t u;
    asm("cvt.rna.tf32.f32 %0, %1;" : "=r"(u) : "f"(x));
    return __uint_as_float(u);
}

__device__ __forceinline__ void cp_async16(void* sdst, const void* gsrc) {
    uint32_t d = (uint32_t)__cvta_generic_to_shared(sdst);
    asm volatile("cp.async.cg.shared.global [%0], [%1], 16;" :: "r"(d), "l"(gsrc));
}
// zero-fill variant: copies src_size bytes (0 or 16), zero-fills the rest
__device__ __forceinline__ void cp_async16z(void* sdst, const void* gsrc, int sz) {
    uint32_t d = (uint32_t)__cvta_generic_to_shared(sdst);
    asm volatile("cp.async.cg.shared.global [%0], [%1], 16, %2;" :: "r"(d), "l"(gsrc), "r"(sz));
}
#define CP_COMMIT() asm volatile("cp.async.commit_group;")
#define CP_WAIT(n)  asm volatile("cp.async.wait_group %0;" :: "n"(n))

// ---------------------------------------------------------------------------
// Kernel 1: segment offsets via binary search (seg sorted)
// ---------------------------------------------------------------------------
__global__ void offsets_kernel(const int* __restrict__ seg) {
    int i = blockIdx.x * blockDim.x + threadIdx.x;
    if (i > NB) return;
    int lo = 0, hi = NE;
    while (lo < hi) {
        int mid = (lo + hi) >> 1;
        if (seg[mid] < i) lo = mid + 1; else hi = mid;
    }
    g_off[i] = lo;
}

// ---------------------------------------------------------------------------
// Kernel 2: build Wcat [960 x 320]: wcat[s*320+j][k] = tf32(W1[j][s*300+k])
// (rows j>=300 of each section are zero -> proj pad halves are exact zeros)
// ---------------------------------------------------------------------------
__global__ void wcat_kernel(const float* __restrict__ W1) {
    int c = blockIdx.x, k = threadIdx.x;       // grid=960, block=320
    int sec = c / 320, j = c - sec * 320;
    float v = 0.0f;
    if (j < DIM && k < DIM) v = tf32r(W1[(size_t)j * (3 * DIM) + sec * DIM + k]);
    g_wcat[(size_t)c * KA + k] = v;
}

// ---------------------------------------------------------------------------
// Kernel 3: parallel fallback rowsums
// ---------------------------------------------------------------------------
__global__ void rowsum_kernel(const float* __restrict__ W1) {
    int j = blockIdx.x;
    int w = threadIdx.x >> 5, lane = threadIdx.x & 31;
    const float* base = W1 + (size_t)j * (3 * DIM) + DIM + w * DIM;
    float s = 0.f;
    for (int k = lane; k < DIM; k += 32) s += base[k];
#pragma unroll
    for (int o = 16; o; o >>= 1) s += __shfl_xor_sync(0xffffffffu, s, o);
    if (lane == 0) {
        if (w == 0) g_rsB[j] = s; else g_rsC[j] = s;
    }
}

// ---------------------------------------------------------------------------
// Kernel 4: GEMM  proj[MPAD,960](fp16) = emb(padded) @ wcat^T
// tf32 mma m16n8k8; BM=128, BN=96, BK=32; 4 warps (2m x 2n), warp tile 64x48
// A fed as raw f32 bits (HW truncates to tf32); B pre-rounded RNA in wcat.
// ---------------------------------------------------------------------------
#define BM 128
#define BN 96
#define BK 32
#define NT (KA / BK)       // 10
#define A_BUF (BM * BK)    // 4096 floats
#define B_BUF (BN * BK)    // 3072 floats
#define GEMM_SMEM ((2 * A_BUF + 2 * B_BUF) * 4)   // 57344 bytes

__device__ __forceinline__ void load_tiles(const float* __restrict__ emb,
                                           const float* __restrict__ Bg,
                                           float* sA, float* sB,
                                           int bmBase, int kt, int tid) {
    int colBase = kt * BK;
#pragma unroll
    for (int i = 0; i < 8; i++) {              // A: 128x32 = 1024 float4
        int lin = tid + i * 128;
        int row = lin >> 3, c4 = lin & 7;
        int gr  = bmBase + row;
        int col = colBase + c4 * 4;
        bool valid = (gr < NUM_NODES) && (col < DIM);
        const float* src = valid ? emb + (size_t)gr * DIM + col : emb;
        int scol = (c4 * 4) ^ ((row & 7) << 2);
        cp_async16z(&sA[row * BK + scol], src, valid ? 16 : 0);
    }
#pragma unroll
    for (int i = 0; i < 6; i++) {              // B: 96x32 = 768 float4
        int lin = tid + i * 128;
        int row = lin >> 3, c4 = lin & 7;
        int scol = (c4 * 4) ^ ((row & 7) << 2);
        cp_async16(&sB[row * BK + scol], Bg + (size_t)row * KA + colBase + c4 * 4);
    }
}

__global__ void __launch_bounds__(128) proj_gemm_kernel(const float* __restrict__ emb) {
    extern __shared__ float sm[];
    float* sA = sm;                 // [2][BM][BK]
    float* sB = sm + 2 * A_BUF;     // [2][BN][BK]

    int bn = blockIdx.x;      // 0..9
    int bm = blockIdx.y;      // 0..227
    int tid = threadIdx.x;
    int warp = tid >> 5, lane = tid & 31;
    int wm = warp & 1, wn = warp >> 1;
    int gid = lane >> 2, tig = lane & 3;

    int bmBase = bm * BM;
    const float* Bg = g_wcat + (size_t)(bn * BN) * KA;

    float c[4][6][4];
#pragma unroll
    for (int mt = 0; mt < 4; mt++)
#pragma unroll
        for (int nt = 0; nt < 6; nt++)
#pragma unroll
            for (int i = 0; i < 4; i++) c[mt][nt][i] = 0.f;

    load_tiles(emb, Bg, sA, sB, bmBase, 0, tid);
    CP_COMMIT();

    for (int kt = 0; kt < NT; kt++) {
        int buf = kt & 1;
        if (kt + 1 < NT) {
            load_tiles(emb, Bg, sA + (buf ^ 1) * A_BUF, sB + (buf ^ 1) * B_BUF,
                       bmBase, kt + 1, tid);
            CP_COMMIT();
            CP_WAIT(1);
        } else {
            CP_WAIT(0);
        }
        __syncthreads();

        const float* Ab = sA + buf * A_BUF;
        const float* Bb = sB + buf * B_BUF;

#pragma unroll
        for (int ks = 0; ks < 4; ks++) {
            int k0 = ks * 8;
            uint32_t a[4][4], bfr[6][2];
#pragma unroll
            for (int mt = 0; mt < 4; mt++) {
                int r0 = wm * 64 + mt * 16 + gid;
                int x = (r0 & 7) << 2;           // (r0+8)&7 == r0&7
                a[mt][0] = __float_as_uint(Ab[r0 * BK + ((k0 + tig) ^ x)]);
                a[mt][1] = __float_as_uint(Ab[(r0 + 8) * BK + ((k0 + tig) ^ x)]);
                a[mt][2] = __float_as_uint(Ab[r0 * BK + ((k0 + tig + 4) ^ x)]);
                a[mt][3] = __float_as_uint(Ab[(r0 + 8) * BK + ((k0 + tig + 4) ^ x)]);
            }
#pragma unroll
            for (int nt = 0; nt < 6; nt++) {
                int n = wn * 48 + nt * 8 + gid;
                int x = (n & 7) << 2;
                bfr[nt][0] = __float_as_uint(Bb[n * BK + ((k0 + tig) ^ x)]);
                bfr[nt][1] = __float_as_uint(Bb[n * BK + ((k0 + tig + 4) ^ x)]);
            }
#pragma unroll
            for (int mt = 0; mt < 4; mt++)
#pragma unroll
                for (int nt = 0; nt < 6; nt++) {
                    asm volatile(
                        "mma.sync.aligned.m16n8k8.row.col.f32.tf32.tf32.f32 "
                        "{%0,%1,%2,%3},{%4,%5,%6,%7},{%8,%9},{%0,%1,%2,%3};"
                        : "+f"(c[mt][nt][0]), "+f"(c[mt][nt][1]),
                          "+f"(c[mt][nt][2]), "+f"(c[mt][nt][3])
                        : "r"(a[mt][0]), "r"(a[mt][1]), "r"(a[mt][2]), "r"(a[mt][3]),
                          "r"(bfr[nt][0]), "r"(bfr[nt][1]));
                }
        }
        __syncthreads();
    }

    // Epilogue: fp16 store (bias added later in agg)
#pragma unroll
    for (int mt = 0; mt < 4; mt++) {
#pragma unroll
        for (int nt = 0; nt < 6; nt++) {
            int gm = bmBase + wm * 64 + mt * 16 + gid;
            int gn = bn * BN + wn * 48 + nt * 8 + tig * 2;
            __half2 h0 = __floats2half2_rn(c[mt][nt][0], c[mt][nt][1]);
            __half2 h1 = __floats2half2_rn(c[mt][nt][2], c[mt][nt][3]);
            *(__half2*)(g_proj + (size_t)gm * PSTR + gn) = h0;
            *(__half2*)(g_proj + (size_t)(gm + 8) * PSTR + gn) = h1;
        }
    }
}

// ---------------------------------------------------------------------------
// Kernel 5: aggregation. Persistent CTAs; 80 threads, thread = 4 dims (uint2).
// Edges block-uniform (type branch warp-uniform, coalesced 640B row reads).
// 16-edge chunks accumulated in fp16 (__hadd2), flushed to fp32 per chunk.
// ---------------------------------------------------------------------------
#define CHUNK 16
#define AGG_T 80
#define AGG_GRID 2048

__global__ void __launch_bounds__(AGG_T) agg_kernel(
    const int* __restrict__ nodes,
    const int* __restrict__ neighbors,
    const float* __restrict__ b1,
    float* __restrict__ out)
{
    int tid = threadIdx.x;
    const __half2 z2 = __float2half2_rn(0.f);

    for (int b = blockIdx.x; b < NB; b += AGG_GRID) {
        int start = g_off[b];
        int end   = g_off[b + 1];
        int node  = nodes[b];
        bool selfA = node < NUM_AUTHOR;

        float2 a1l = {0.f, 0.f}, a1h = {0.f, 0.f};
        float2 a2l = {0.f, 0.f}, a2h = {0.f, 0.f};
        int c1 = 0;

        int e = start;
        for (; e + CHUNK <= end; e += CHUNK) {
            int  nn[CHUNK];
            bool ss[CHUNK];
            uint2 h[CHUNK];
#pragma unroll
            for (int j = 0; j < CHUNK; j++) nn[j] = neighbors[e + j];
#pragma unroll
            for (int j = 0; j < CHUNK; j++) {
                ss[j] = (nn[j] < NUM_AUTHOR) == selfA;
                h[j] = *((const uint2*)(g_proj + (size_t)nn[j] * PSTR + (ss[j] ? 320 : 640)) + tid);
            }
            __half2 p1l = z2, p1h = z2, p2l = z2, p2h = z2;
#pragma unroll
            for (int j = 0; j < CHUNK; j++) {
                const __half2* hv = (const __half2*)&h[j];
                if (ss[j]) { p1l = __hadd2(p1l, hv[0]); p1h = __hadd2(p1h, hv[1]); c1++; }
                else       { p2l = __hadd2(p2l, hv[0]); p2h = __hadd2(p2h, hv[1]); }
            }
            float2 f;
            f = __half22float2(p1l); a1l.x += f.x; a1l.y += f.y;
            f = __half22float2(p1h); a1h.x += f.x; a1h.y += f.y;
            f = __half22float2(p2l); a2l.x += f.x; a2l.y += f.y;
            f = __half22float2(p2h); a2h.x += f.x; a2h.y += f.y;
        }
        // remainder (< CHUNK edges)
        {
            __half2 p1l = z2, p1h = z2, p2l = z2, p2h = z2;
            for (; e < end; e++) {
                int n = neighbors[e];
                bool s = (n < NUM_AUTHOR) == selfA;
                uint2 v = *((const uint2*)(g_proj + (size_t)n * PSTR + (s ? 320 : 640)) + tid);
                const __half2* hv = (const __half2*)&v;
                if (s) { p1l = __hadd2(p1l, hv[0]); p1h = __hadd2(p1h, hv[1]); c1++; }
                else   { p2l = __hadd2(p2l, hv[0]); p2h = __hadd2(p2h, hv[1]); }
            }
            float2 f;
            f = __half22float2(p1l); a1l.x += f.x; a1l.y += f.y;
            f = __half22float2(p1h); a1h.x += f.x; a1h.y += f.y;
            f = __half22float2(p2l); a2l.x += f.x; a2l.y += f.y;
            f = __half22float2(p2h); a2h.x += f.x; a2h.y += f.y;
        }

        if (tid < 75) {                       // dims [tid*4, tid*4+4) < 300
            int tot = end - start;
            int c2 = tot - c1;
            int d = tid * 4;
            float t1[4], t2[4];
            if (c1 > 0) {
                float r = 1.0f / (float)c1;
                t1[0] = a1l.x * r; t1[1] = a1l.y * r; t1[2] = a1h.x * r; t1[3] = a1h.y * r;
            } else {
                t1[0] = g_rsB[d]; t1[1] = g_rsB[d + 1]; t1[2] = g_rsB[d + 2]; t1[3] = g_rsB[d + 3];
            }
            if (c2 > 0) {
                float r = 1.0f / (float)c2;
                t2[0] = a2l.x * r; t2[1] = a2l.y * r; t2[2] = a2h.x * r; t2[3] = a2h.y * r;
            } else {
                t2[0] = g_rsC[d]; t2[1] = g_rsC[d + 1]; t2[2] = g_rsC[d + 2]; t2[3] = g_rsC[d + 3];
            }

            uint2 sv = *((const uint2*)(g_proj + (size_t)node * PSTR) + tid);
            const __half2* sp = (const __half2*)&sv;
            float2 s0 = __half22float2(sp[0]);
            float2 s1 = __half22float2(sp[1]);
            float4 bb = *(const float4*)(b1 + d);

            float4 o;
            o.x = s0.x + t1[0] + t2[0] + bb.x;
            o.y = s0.y + t1[1] + t2[1] + bb.y;
            o.z = s1.x + t1[2] + t2[2] + bb.z;
            o.w = s1.y + t1[3] + t2[3] + bb.w;
            *(float4*)(out + (size_t)b * DIM + d) = o;   // (b*300+d) % 4 == 0
        }
    }
}

// ---------------------------------------------------------------------------
extern "C" void kernel_launch(void* const* d_in, const int* in_sizes, int n_in,
                              void* d_out, int out_size) {
    const int*   nodes     = (const int*)d_in[0];
    const int*   seg       = (const int*)d_in[1];
    const int*   neighbors = (const int*)d_in[2];
    const float* emb       = (const float*)d_in[3];
    const float* W1        = (const float*)d_in[4];
    const float* b1        = (const float*)d_in[5];
    float*       out       = (float*)d_out;

    cudaFuncSetAttribute(proj_gemm_kernel,
                         cudaFuncAttributeMaxDynamicSharedMemorySize, GEMM_SMEM);

    offsets_kernel<<<(NB + 1 + 255) / 256, 256>>>(seg);
    wcat_kernel<<<NPADC, 320>>>(W1);
    rowsum_kernel<<<DIM, 64>>>(W1);
    dim3 ggrid(NPADC / BN, MPAD / BM);   // (10, 228), x-fast shares A via L2
    proj_gemm_kernel<<<ggrid, 128, GEMM_SMEM>>>(emb);
    agg_kernel<<<AGG_GRID, AGG_T>>>(nodes, neighbors, b1, out);
}

// round 10
// speedup vs baseline: 1.2011x; 1.2011x over previous
#include <cuda_runtime.h>
#include <cuda_fp16.h>
#include <cstdint>

// Problem constants
#define NUM_AUTHOR 16604
#define NUM_NODES  29059
#define DIM        300
#define NB         32768
#define NE         1048576

// GEMM shape: proj = emb[29059,300] @ Wcat[960,300]^T  (padded M=29184, K=320)
#define MPAD  29184        // 228 * 128
#define KH    320          // padded K (halves)
#define NPADC 960          // 3 sections x 320 cols
#define PSTR  960          // proj row stride (halves)

// Scratch (device globals; allocation-free rule)
__device__ __half g_embh[(size_t)MPAD * KH];     // fp16 emb, fully zero-padded (18.7 MB)
__device__ __half g_wcath[(size_t)NPADC * KH];   // fp16 remapped W1
__device__ __half g_proj[(size_t)MPAD * PSTR];   // projected table, fp16 (56 MB)
__device__ float  g_rsB[DIM];                    // rowsum of Wb (empty-type-1 fallback)
__device__ float  g_rsC[DIM];                    // rowsum of Wc (empty-type-2 fallback)
__device__ int    g_off[NB + 1];

__device__ __forceinline__ void cp_async16(void* sdst, const void* gsrc) {
    uint32_t d = (uint32_t)__cvta_generic_to_shared(sdst);
    asm volatile("cp.async.cg.shared.global [%0], [%1], 16;" :: "r"(d), "l"(gsrc));
}
#define CP_COMMIT() asm volatile("cp.async.commit_group;")
#define CP_WAIT(n)  asm volatile("cp.async.wait_group %0;" :: "n"(n))

// ---------------------------------------------------------------------------
// Kernel 1: segment offsets via binary search (seg sorted)
// ---------------------------------------------------------------------------
__global__ void offsets_kernel(const int* __restrict__ seg) {
    int i = blockIdx.x * blockDim.x + threadIdx.x;
    if (i > NB) return;
    int lo = 0, hi = NE;
    while (lo < hi) {
        int mid = (lo + hi) >> 1;
        if (seg[mid] < i) lo = mid + 1; else hi = mid;
    }
    g_off[i] = lo;
}

// ---------------------------------------------------------------------------
// Kernel 2: emb -> fp16, zero-padded to [MPAD][320]
// ---------------------------------------------------------------------------
__global__ void embh_kernel(const float* __restrict__ emb) {
    int row = blockIdx.x, t = threadIdx.x;     // grid=MPAD, block=160
    int k = 2 * t;
    float v0 = 0.f, v1 = 0.f;
    if (row < NUM_NODES && k < DIM) {
        v0 = emb[(size_t)row * DIM + k];
        if (k + 1 < DIM) v1 = emb[(size_t)row * DIM + k + 1];
    }
    *(__half2*)(g_embh + (size_t)row * KH + k) = __floats2half2_rn(v0, v1);
}

// ---------------------------------------------------------------------------
// Kernel 3: Wcat fp16 [960 x 320]: wcath[s*320+j][k] = h(W1[j][s*300+k])
// (rows j>=300 of each section zero -> proj pad halves are exact zeros)
// ---------------------------------------------------------------------------
__global__ void wcath_kernel(const float* __restrict__ W1) {
    int c = blockIdx.x, t = threadIdx.x;       // grid=960, block=160
    int sec = c / 320, j = c - sec * 320;
    int k = 2 * t;
    float v0 = 0.f, v1 = 0.f;
    if (j < DIM && k < DIM) {
        v0 = W1[(size_t)j * (3 * DIM) + sec * DIM + k];
        if (k + 1 < DIM) v1 = W1[(size_t)j * (3 * DIM) + sec * DIM + k + 1];
    }
    *(__half2*)(g_wcath + (size_t)c * KH + k) = __floats2half2_rn(v0, v1);
}

// ---------------------------------------------------------------------------
// Kernel 4: parallel fallback rowsums
// ---------------------------------------------------------------------------
__global__ void rowsum_kernel(const float* __restrict__ W1) {
    int j = blockIdx.x;
    int w = threadIdx.x >> 5, lane = threadIdx.x & 31;
    const float* base = W1 + (size_t)j * (3 * DIM) + DIM + w * DIM;
    float s = 0.f;
    for (int k = lane; k < DIM; k += 32) s += base[k];
#pragma unroll
    for (int o = 16; o; o >>= 1) s += __shfl_xor_sync(0xffffffffu, s, o);
    if (lane == 0) {
        if (w == 0) g_rsB[j] = s; else g_rsC[j] = s;
    }
}

// ---------------------------------------------------------------------------
// Kernel 5: GEMM  proj[MPAD,960](fp16) = embh @ wcath^T   (fp16 in, fp32 acc)
// mma m16n8k16.f16; BM=128, BN=96, BK=32 halves; 4 warps (2m x 2n), wtile 64x48
// 16B-chunk XOR swizzle: chunk ^ ((row>>1)&3)  (conflict-free fragment LDS)
// ---------------------------------------------------------------------------
#define BM 128
#define BN 96
#define BKH 32             // halves per K tile
#define NT (KH / BKH)      // 10
#define A_BUFH (BM * BKH)  // 4096 halves (8 KB)
#define B_BUFH (BN * BKH)  // 3072 halves (6 KB)

__device__ __forceinline__ uint32_t lds_h2(const __half* base, int r, int k) {
    int off = r * BKH + ((((k >> 3) ^ ((r >> 1) & 3))) << 3) + (k & 7);
    return *(const uint32_t*)(base + off);
}

__device__ __forceinline__ void load_tiles(const __half* __restrict__ Ag,
                                           const __half* __restrict__ Bg,
                                           __half* sA, __half* sB,
                                           int kt, int tid) {
    int kb = kt * BKH;
#pragma unroll
    for (int i = 0; i < 4; i++) {              // A: 512 16B chunks
        int lin = tid + i * 128;
        int r = lin >> 2, c = lin & 3;
        int sc = c ^ ((r >> 1) & 3);
        cp_async16(sA + r * BKH + sc * 8, Ag + (size_t)r * KH + kb + c * 8);
    }
#pragma unroll
    for (int i = 0; i < 3; i++) {              // B: 384 16B chunks
        int lin = tid + i * 128;
        int r = lin >> 2, c = lin & 3;
        int sc = c ^ ((r >> 1) & 3);
        cp_async16(sB + r * BKH + sc * 8, Bg + (size_t)r * KH + kb + c * 8);
    }
}

__global__ void __launch_bounds__(128) proj_gemm_kernel() {
    __shared__ __half sA[2][A_BUFH];   // 16 KB
    __shared__ __half sB[2][B_BUFH];   // 12 KB

    int bn = blockIdx.x;      // 0..9
    int bm = blockIdx.y;      // 0..227
    int tid = threadIdx.x;
    int warp = tid >> 5, lane = tid & 31;
    int wm = warp & 1, wn = warp >> 1;
    int gid = lane >> 2, tig = lane & 3;

    int bmBase = bm * BM;
    const __half* Ag = g_embh + (size_t)bmBase * KH;
    const __half* Bg = g_wcath + (size_t)(bn * BN) * KH;

    float c[4][6][4];
#pragma unroll
    for (int mt = 0; mt < 4; mt++)
#pragma unroll
        for (int nt = 0; nt < 6; nt++)
#pragma unroll
            for (int i = 0; i < 4; i++) c[mt][nt][i] = 0.f;

    load_tiles(Ag, Bg, sA[0], sB[0], 0, tid);
    CP_COMMIT();

    for (int kt = 0; kt < NT; kt++) {
        int buf = kt & 1;
        if (kt + 1 < NT) {
            load_tiles(Ag, Bg, sA[buf ^ 1], sB[buf ^ 1], kt + 1, tid);
            CP_COMMIT();
            CP_WAIT(1);
        } else {
            CP_WAIT(0);
        }
        __syncthreads();

        const __half* Ab = sA[buf];
        const __half* Bb = sB[buf];

#pragma unroll
        for (int ks = 0; ks < 2; ks++) {
            int k0 = ks * 16;
            uint32_t a[4][4], bfr[6][2];
#pragma unroll
            for (int mt = 0; mt < 4; mt++) {
                int r0 = wm * 64 + mt * 16 + gid;
                a[mt][0] = lds_h2(Ab, r0,     k0 + 2 * tig);
                a[mt][1] = lds_h2(Ab, r0 + 8, k0 + 2 * tig);
                a[mt][2] = lds_h2(Ab, r0,     k0 + 8 + 2 * tig);
                a[mt][3] = lds_h2(Ab, r0 + 8, k0 + 8 + 2 * tig);
            }
#pragma unroll
            for (int nt = 0; nt < 6; nt++) {
                int n = wn * 48 + nt * 8 + gid;
                bfr[nt][0] = lds_h2(Bb, n, k0 + 2 * tig);
                bfr[nt][1] = lds_h2(Bb, n, k0 + 8 + 2 * tig);
            }
#pragma unroll
            for (int mt = 0; mt < 4; mt++)
#pragma unroll
                for (int nt = 0; nt < 6; nt++) {
                    asm volatile(
                        "mma.sync.aligned.m16n8k16.row.col.f32.f16.f16.f32 "
                        "{%0,%1,%2,%3},{%4,%5,%6,%7},{%8,%9},{%0,%1,%2,%3};"
                        : "+f"(c[mt][nt][0]), "+f"(c[mt][nt][1]),
                          "+f"(c[mt][nt][2]), "+f"(c[mt][nt][3])
                        : "r"(a[mt][0]), "r"(a[mt][1]), "r"(a[mt][2]), "r"(a[mt][3]),
                          "r"(bfr[nt][0]), "r"(bfr[nt][1]));
                }
        }
        __syncthreads();
    }

    // Epilogue: fp16 store (bias added later in agg)
#pragma unroll
    for (int mt = 0; mt < 4; mt++) {
#pragma unroll
        for (int nt = 0; nt < 6; nt++) {
            int gm = bmBase + wm * 64 + mt * 16 + gid;
            int gn = bn * BN + wn * 48 + nt * 8 + tig * 2;
            __half2 h0 = __floats2half2_rn(c[mt][nt][0], c[mt][nt][1]);
            __half2 h1 = __floats2half2_rn(c[mt][nt][2], c[mt][nt][3]);
            *(__half2*)(g_proj + (size_t)gm * PSTR + gn) = h0;
            *(__half2*)(g_proj + (size_t)(gm + 8) * PSTR + gn) = h1;
        }
    }
}

// ---------------------------------------------------------------------------
// Kernel 6: aggregation (R8 version, verbatim structure: block = node,
// 160 threads, thread = half2 slot; edges block-uniform; 16-edge fp16 chunks)
// ---------------------------------------------------------------------------
#define CHUNK 16

__global__ void __launch_bounds__(160) agg_kernel(
    const int* __restrict__ nodes,
    const int* __restrict__ neighbors,
    const float* __restrict__ b1,
    float* __restrict__ out)
{
    int b = blockIdx.x;
    int tid = threadIdx.x;
    int start = g_off[b];
    int end   = g_off[b + 1];
    int node  = nodes[b];
    bool selfA = node < NUM_AUTHOR;

    float2 a1 = {0.f, 0.f}, a2 = {0.f, 0.f};
    int c1 = 0;
    const __half2 z2 = __float2half2_rn(0.f);

    int e = start;
    for (; e + CHUNK <= end; e += CHUNK) {
        int  nn[CHUNK];
        bool ss[CHUNK];
        __half2 h[CHUNK];
#pragma unroll
        for (int j = 0; j < CHUNK; j++) nn[j] = neighbors[e + j];
#pragma unroll
        for (int j = 0; j < CHUNK; j++) {
            ss[j] = (nn[j] < NUM_AUTHOR) == selfA;
            h[j] = *((const __half2*)(g_proj + (size_t)nn[j] * PSTR + (ss[j] ? 320 : 640)) + tid);
        }
        __half2 p1 = z2, p2 = z2;
#pragma unroll
        for (int j = 0; j < CHUNK; j++) {
            if (ss[j]) { p1 = __hadd2(p1, h[j]); c1++; }
            else       { p2 = __hadd2(p2, h[j]); }
        }
        float2 f1 = __half22float2(p1);
        float2 f2 = __half22float2(p2);
        a1.x += f1.x; a1.y += f1.y;
        a2.x += f2.x; a2.y += f2.y;
    }
    // remainder (< CHUNK edges)
    {
        __half2 p1 = z2, p2 = z2;
        for (; e < end; e++) {
            int n = neighbors[e];
            bool s = (n < NUM_AUTHOR) == selfA;
            __half2 h = *((const __half2*)(g_proj + (size_t)n * PSTR + (s ? 320 : 640)) + tid);
            if (s) { p1 = __hadd2(p1, h); c1++; }
            else   { p2 = __hadd2(p2, h); }
        }
        float2 f1 = __half22float2(p1);
        float2 f2 = __half22float2(p2);
        a1.x += f1.x; a1.y += f1.y;
        a2.x += f2.x; a2.y += f2.y;
    }

    if (tid * 2 < DIM) {
        int tot = end - start;
        int c2 = tot - c1;
        float2 t1, t2;
        if (c1 > 0) { float r = 1.0f / (float)c1; t1.x = a1.x * r; t1.y = a1.y * r; }
        else        { t1.x = g_rsB[2 * tid];      t1.y = g_rsB[2 * tid + 1]; }
        if (c2 > 0) { float r = 1.0f / (float)c2; t2.x = a2.x * r; t2.y = a2.y * r; }
        else        { t2.x = g_rsC[2 * tid];      t2.y = g_rsC[2 * tid + 1]; }

        __half2 sh = *((const __half2*)(g_proj + (size_t)node * PSTR) + tid);
        float2 sf = __half22float2(sh);
        float2 bb = *(const float2*)(b1 + 2 * tid);
        float2 o;
        o.x = sf.x + t1.x + t2.x + bb.x;
        o.y = sf.y + t1.y + t2.y + bb.y;
        *(float2*)(out + (size_t)b * DIM + 2 * tid) = o;
    }
}

// ---------------------------------------------------------------------------
extern "C" void kernel_launch(void* const* d_in, const int* in_sizes, int n_in,
                              void* d_out, int out_size) {
    const int*   nodes     = (const int*)d_in[0];
    const int*   seg       = (const int*)d_in[1];
    const int*   neighbors = (const int*)d_in[2];
    const float* emb       = (const float*)d_in[3];
    const float* W1        = (const float*)d_in[4];
    const float* b1        = (const float*)d_in[5];
    float*       out       = (float*)d_out;

    offsets_kernel<<<(NB + 1 + 255) / 256, 256>>>(seg);
    embh_kernel<<<MPAD, 160>>>(emb);
    wcath_kernel<<<NPADC, 160>>>(W1);
    rowsum_kernel<<<DIM, 64>>>(W1);
    dim3 ggrid(NPADC / BN, MPAD / BM);   // (10, 228), x-fast shares A via L2
    proj_gemm_kernel<<<ggrid, 128>>>();
    agg_kernel<<<NB, 160>>>(nodes, neighbors, b1, out);
}

// round 11
// speedup vs baseline: 1.2914x; 1.0752x over previous
#include <cuda_runtime.h>
#include <cuda_fp16.h>
#include <cstdint>

// Problem constants
#define NUM_AUTHOR 16604
#define NUM_NODES  29059
#define DIM        300
#define NB         32768
#define NE         1048576

// GEMM shape: proj = emb[29059,300] @ Wcat[960,300]^T  (padded M=29184, K=320)
#define MPAD  29184        // 228 * 128
#define KH    320          // padded K (halves)
#define NPADC 960          // 3 sections x 320 cols
#define PSTR  960          // proj row stride (halves)

// Scratch (device globals; allocation-free rule)
__device__ __half g_embh[(size_t)MPAD * KH];     // fp16 emb, fully zero-padded (18.7 MB)
__device__ __half g_wcath[(size_t)NPADC * KH];   // fp16 remapped W1
__device__ __half g_proj[(size_t)MPAD * PSTR];   // projected table, fp16 (56 MB)
__device__ float  g_rsB[DIM];                    // rowsum of Wb (empty-type-1 fallback)
__device__ float  g_rsC[DIM];                    // rowsum of Wc (empty-type-2 fallback)
__device__ int    g_off[NB + 1];

__device__ __forceinline__ void cp_async16(void* sdst, const void* gsrc) {
    uint32_t d = (uint32_t)__cvta_generic_to_shared(sdst);
    asm volatile("cp.async.cg.shared.global [%0], [%1], 16;" :: "r"(d), "l"(gsrc));
}
#define CP_COMMIT() asm volatile("cp.async.commit_group;")
#define CP_WAIT(n)  asm volatile("cp.async.wait_group %0;" :: "n"(n))

// ---------------------------------------------------------------------------
// Kernel 1: segment offsets via binary search (seg sorted)
// ---------------------------------------------------------------------------
__global__ void offsets_kernel(const int* __restrict__ seg) {
    int i = blockIdx.x * blockDim.x + threadIdx.x;
    if (i > NB) return;
    int lo = 0, hi = NE;
    while (lo < hi) {
        int mid = (lo + hi) >> 1;
        if (seg[mid] < i) lo = mid + 1; else hi = mid;
    }
    g_off[i] = lo;
}

// ---------------------------------------------------------------------------
// Kernel 2: emb -> fp16, zero-padded to [MPAD][320]
// ---------------------------------------------------------------------------
__global__ void embh_kernel(const float* __restrict__ emb) {
    int row = blockIdx.x, t = threadIdx.x;     // grid=MPAD, block=160
    int k = 2 * t;
    float v0 = 0.f, v1 = 0.f;
    if (row < NUM_NODES && k < DIM) {
        v0 = emb[(size_t)row * DIM + k];
        if (k + 1 < DIM) v1 = emb[(size_t)row * DIM + k + 1];
    }
    *(__half2*)(g_embh + (size_t)row * KH + k) = __floats2half2_rn(v0, v1);
}

// ---------------------------------------------------------------------------
// Kernel 3: Wcat fp16 [960 x 320]: wcath[s*320+j][k] = h(W1[j][s*300+k])
// ---------------------------------------------------------------------------
__global__ void wcath_kernel(const float* __restrict__ W1) {
    int c = blockIdx.x, t = threadIdx.x;       // grid=960, block=160
    int sec = c / 320, j = c - sec * 320;
    int k = 2 * t;
    float v0 = 0.f, v1 = 0.f;
    if (j < DIM && k < DIM) {
        v0 = W1[(size_t)j * (3 * DIM) + sec * DIM + k];
        if (k + 1 < DIM) v1 = W1[(size_t)j * (3 * DIM) + sec * DIM + k + 1];
    }
    *(__half2*)(g_wcath + (size_t)c * KH + k) = __floats2half2_rn(v0, v1);
}

// ---------------------------------------------------------------------------
// Kernel 4: parallel fallback rowsums: 1 warp per (j, sec), 8 warps/block
// ---------------------------------------------------------------------------
__global__ void rowsum_kernel(const float* __restrict__ W1) {
    int w = threadIdx.x >> 5, lane = threadIdx.x & 31;
    int p = blockIdx.x * 8 + w;                // 0..599
    int j = p >> 1, sec = p & 1;
    const float* base = W1 + (size_t)j * (3 * DIM) + DIM + sec * DIM;
    float s = 0.f;
    for (int k = lane; k < DIM; k += 32) s += base[k];
#pragma unroll
    for (int o = 16; o; o >>= 1) s += __shfl_xor_sync(0xffffffffu, s, o);
    if (lane == 0) {
        if (sec == 0) g_rsB[j] = s; else g_rsC[j] = s;
    }
}

// ---------------------------------------------------------------------------
// Kernel 5: GEMM  proj[MPAD,960](fp16) = embh @ wcath^T   (fp16 in, fp32 acc)
// mma m16n8k16.f16; BM=128, BN=96, BKH=32; 4 warps (2m x 2n), wtile 64x48
// 16B-chunk XOR swizzle: chunk ^ ((row>>1)&3)
// ---------------------------------------------------------------------------
#define BM 128
#define BN 96
#define BKH 32             // halves per K tile
#define NT (KH / BKH)      // 10
#define A_BUFH (BM * BKH)  // 4096 halves (8 KB)
#define B_BUFH (BN * BKH)  // 3072 halves (6 KB)

__device__ __forceinline__ uint32_t lds_h2(const __half* base, int r, int k) {
    int off = r * BKH + ((((k >> 3) ^ ((r >> 1) & 3))) << 3) + (k & 7);
    return *(const uint32_t*)(base + off);
}

__device__ __forceinline__ void load_tiles(const __half* __restrict__ Ag,
                                           const __half* __restrict__ Bg,
                                           __half* sA, __half* sB,
                                           int kt, int tid) {
    int kb = kt * BKH;
#pragma unroll
    for (int i = 0; i < 4; i++) {              // A: 512 16B chunks
        int lin = tid + i * 128;
        int r = lin >> 2, c = lin & 3;
        int sc = c ^ ((r >> 1) & 3);
        cp_async16(sA + r * BKH + sc * 8, Ag + (size_t)r * KH + kb + c * 8);
    }
#pragma unroll
    for (int i = 0; i < 3; i++) {              // B: 384 16B chunks
        int lin = tid + i * 128;
        int r = lin >> 2, c = lin & 3;
        int sc = c ^ ((r >> 1) & 3);
        cp_async16(sB + r * BKH + sc * 8, Bg + (size_t)r * KH + kb + c * 8);
    }
}

__global__ void __launch_bounds__(128) proj_gemm_kernel() {
    __shared__ __half sA[2][A_BUFH];   // 16 KB
    __shared__ __half sB[2][B_BUFH];   // 12 KB

    int bn = blockIdx.x;      // 0..9
    int bm = blockIdx.y;      // 0..227
    int tid = threadIdx.x;
    int warp = tid >> 5, lane = tid & 31;
    int wm = warp & 1, wn = warp >> 1;
    int gid = lane >> 2, tig = lane & 3;

    int bmBase = bm * BM;
    const __half* Ag = g_embh + (size_t)bmBase * KH;
    const __half* Bg = g_wcath + (size_t)(bn * BN) * KH;

    float c[4][6][4];
#pragma unroll
    for (int mt = 0; mt < 4; mt++)
#pragma unroll
        for (int nt = 0; nt < 6; nt++)
#pragma unroll
            for (int i = 0; i < 4; i++) c[mt][nt][i] = 0.f;

    load_tiles(Ag, Bg, sA[0], sB[0], 0, tid);
    CP_COMMIT();

    for (int kt = 0; kt < NT; kt++) {
        int buf = kt & 1;
        if (kt + 1 < NT) {
            load_tiles(Ag, Bg, sA[buf ^ 1], sB[buf ^ 1], kt + 1, tid);
            CP_COMMIT();
            CP_WAIT(1);
        } else {
            CP_WAIT(0);
        }
        __syncthreads();

        const __half* Ab = sA[buf];
        const __half* Bb = sB[buf];

#pragma unroll
        for (int ks = 0; ks < 2; ks++) {
            int k0 = ks * 16;
            uint32_t a[4][4], bfr[6][2];
#pragma unroll
            for (int mt = 0; mt < 4; mt++) {
                int r0 = wm * 64 + mt * 16 + gid;
                a[mt][0] = lds_h2(Ab, r0,     k0 + 2 * tig);
                a[mt][1] = lds_h2(Ab, r0 + 8, k0 + 2 * tig);
                a[mt][2] = lds_h2(Ab, r0,     k0 + 8 + 2 * tig);
                a[mt][3] = lds_h2(Ab, r0 + 8, k0 + 8 + 2 * tig);
            }
#pragma unroll
            for (int nt = 0; nt < 6; nt++) {
                int n = wn * 48 + nt * 8 + gid;
                bfr[nt][0] = lds_h2(Bb, n, k0 + 2 * tig);
                bfr[nt][1] = lds_h2(Bb, n, k0 + 8 + 2 * tig);
            }
#pragma unroll
            for (int mt = 0; mt < 4; mt++)
#pragma unroll
                for (int nt = 0; nt < 6; nt++) {
                    asm volatile(
                        "mma.sync.aligned.m16n8k16.row.col.f32.f16.f16.f32 "
                        "{%0,%1,%2,%3},{%4,%5,%6,%7},{%8,%9},{%0,%1,%2,%3};"
                        : "+f"(c[mt][nt][0]), "+f"(c[mt][nt][1]),
                          "+f"(c[mt][nt][2]), "+f"(c[mt][nt][3])
                        : "r"(a[mt][0]), "r"(a[mt][1]), "r"(a[mt][2]), "r"(a[mt][3]),
                          "r"(bfr[nt][0]), "r"(bfr[nt][1]));
                }
        }
        __syncthreads();
    }

    // Epilogue: fp16 store (bias added later in agg)
#pragma unroll
    for (int mt = 0; mt < 4; mt++) {
#pragma unroll
        for (int nt = 0; nt < 6; nt++) {
            int gm = bmBase + wm * 64 + mt * 16 + gid;
            int gn = bn * BN + wn * 48 + nt * 8 + tig * 2;
            __half2 h0 = __floats2half2_rn(c[mt][nt][0], c[mt][nt][1]);
            __half2 h1 = __floats2half2_rn(c[mt][nt][2], c[mt][nt][3]);
            *(__half2*)(g_proj + (size_t)gm * PSTR + gn) = h0;
            *(__half2*)(g_proj + (size_t)(gm + 8) * PSTR + gn) = h1;
        }
    }
}

// ---------------------------------------------------------------------------
// Kernel 6: aggregation. Block = one node (32k blocks, NOT persistent).
// 80 threads, thread = 4 dims (uint2). Edges block-uniform.
// int4 neighbor-index loads (peel to 16B alignment); 16-edge fp16 chunks.
// ---------------------------------------------------------------------------
#define CHUNK 16
#define AGG_T 80

__global__ void __launch_bounds__(AGG_T) agg_kernel(
    const int* __restrict__ nodes,
    const int* __restrict__ neighbors,
    const float* __restrict__ b1,
    float* __restrict__ out)
{
    int b = blockIdx.x;
    int tid = threadIdx.x;
    int start = g_off[b];
    int end   = g_off[b + 1];
    int node  = nodes[b];
    bool selfA = node < NUM_AUTHOR;
    const __half2 z2 = __float2half2_rn(0.f);

    float2 a1l = {0.f, 0.f}, a1h = {0.f, 0.f};
    float2 a2l = {0.f, 0.f}, a2h = {0.f, 0.f};
    int c1 = 0;

    int e = start;

    // peel to 4-edge (16B) alignment of the index array
    {
        int pre = (4 - (e & 3)) & 3;
        if (pre > end - e) pre = end - e;
        __half2 p1l = z2, p1h = z2, p2l = z2, p2h = z2;
        for (int q = 0; q < pre; q++, e++) {
            int n = neighbors[e];
            bool s = (n < NUM_AUTHOR) == selfA;
            uint2 v = *((const uint2*)(g_proj + (size_t)n * PSTR + (s ? 320 : 640)) + tid);
            const __half2* hv = (const __half2*)&v;
            if (s) { p1l = __hadd2(p1l, hv[0]); p1h = __hadd2(p1h, hv[1]); c1++; }
            else   { p2l = __hadd2(p2l, hv[0]); p2h = __hadd2(p2h, hv[1]); }
        }
        float2 f;
        f = __half22float2(p1l); a1l.x += f.x; a1l.y += f.y;
        f = __half22float2(p1h); a1h.x += f.x; a1h.y += f.y;
        f = __half22float2(p2l); a2l.x += f.x; a2l.y += f.y;
        f = __half22float2(p2h); a2h.x += f.x; a2h.y += f.y;
    }

    // main: 16-edge chunks, indices via 4x LDG.128
    for (; e + CHUNK <= end; e += CHUNK) {
        int4 q0 = *(const int4*)(neighbors + e);
        int4 q1 = *(const int4*)(neighbors + e + 4);
        int4 q2 = *(const int4*)(neighbors + e + 8);
        int4 q3 = *(const int4*)(neighbors + e + 12);
        int nn[CHUNK] = {q0.x, q0.y, q0.z, q0.w, q1.x, q1.y, q1.z, q1.w,
                         q2.x, q2.y, q2.z, q2.w, q3.x, q3.y, q3.z, q3.w};
        bool ss[CHUNK];
        uint2 h[CHUNK];
#pragma unroll
        for (int j = 0; j < CHUNK; j++) {
            ss[j] = (nn[j] < NUM_AUTHOR) == selfA;
            h[j] = *((const uint2*)(g_proj + (size_t)nn[j] * PSTR + (ss[j] ? 320 : 640)) + tid);
        }
        __half2 p1l = z2, p1h = z2, p2l = z2, p2h = z2;
#pragma unroll
        for (int j = 0; j < CHUNK; j++) {
            const __half2* hv = (const __half2*)&h[j];
            if (ss[j]) { p1l = __hadd2(p1l, hv[0]); p1h = __hadd2(p1h, hv[1]); c1++; }
            else       { p2l = __hadd2(p2l, hv[0]); p2h = __hadd2(p2h, hv[1]); }
        }
        float2 f;
        f = __half22float2(p1l); a1l.x += f.x; a1l.y += f.y;
        f = __half22float2(p1h); a1h.x += f.x; a1h.y += f.y;
        f = __half22float2(p2l); a2l.x += f.x; a2l.y += f.y;
        f = __half22float2(p2h); a2h.x += f.x; a2h.y += f.y;
    }

    // remainder (< CHUNK edges)
    {
        __half2 p1l = z2, p1h = z2, p2l = z2, p2h = z2;
        for (; e < end; e++) {
            int n = neighbors[e];
            bool s = (n < NUM_AUTHOR) == selfA;
            uint2 v = *((const uint2*)(g_proj + (size_t)n * PSTR + (s ? 320 : 640)) + tid);
            const __half2* hv = (const __half2*)&v;
            if (s) { p1l = __hadd2(p1l, hv[0]); p1h = __hadd2(p1h, hv[1]); c1++; }
            else   { p2l = __hadd2(p2l, hv[0]); p2h = __hadd2(p2h, hv[1]); }
        }
        float2 f;
        f = __half22float2(p1l); a1l.x += f.x; a1l.y += f.y;
        f = __half22float2(p1h); a1h.x += f.x; a1h.y += f.y;
        f = __half22float2(p2l); a2l.x += f.x; a2l.y += f.y;
        f = __half22float2(p2h); a2h.x += f.x; a2h.y += f.y;
    }

    if (tid < 75) {                       // dims [tid*4, tid*4+4) < 300
        int tot = end - start;
        int c2 = tot - c1;
        int d = tid * 4;
        float t1[4], t2[4];
        if (c1 > 0) {
            float r = 1.0f / (float)c1;
            t1[0] = a1l.x * r; t1[1] = a1l.y * r; t1[2] = a1h.x * r; t1[3] = a1h.y * r;
        } else {
            t1[0] = g_rsB[d]; t1[1] = g_rsB[d + 1]; t1[2] = g_rsB[d + 2]; t1[3] = g_rsB[d + 3];
        }
        if (c2 > 0) {
            float r = 1.0f / (float)c2;
            t2[0] = a2l.x * r; t2[1] = a2l.y * r; t2[2] = a2h.x * r; t2[3] = a2h.y * r;
        } else {
            t2[0] = g_rsC[d]; t2[1] = g_rsC[d + 1]; t2[2] = g_rsC[d + 2]; t2[3] = g_rsC[d + 3];
        }

        uint2 sv = *((const uint2*)(g_proj + (size_t)node * PSTR) + tid);
        const __half2* sp = (const __half2*)&sv;
        float2 s0 = __half22float2(sp[0]);
        float2 s1 = __half22float2(sp[1]);
        float4 bb = *(const float4*)(b1 + d);

        float4 o;
        o.x = s0.x + t1[0] + t2[0] + bb.x;
        o.y = s0.y + t1[1] + t2[1] + bb.y;
        o.z = s1.x + t1[2] + t2[2] + bb.z;
        o.w = s1.y + t1[3] + t2[3] + bb.w;
        *(float4*)(out + (size_t)b * DIM + d) = o;   // (b*300+d) % 4 == 0
    }
}

// ---------------------------------------------------------------------------
extern "C" void kernel_launch(void* const* d_in, const int* in_sizes, int n_in,
                              void* d_out, int out_size) {
    const int*   nodes     = (const int*)d_in[0];
    const int*   seg       = (const int*)d_in[1];
    const int*   neighbors = (const int*)d_in[2];
    const float* emb       = (const float*)d_in[3];
    const float* W1        = (const float*)d_in[4];
    const float* b1        = (const float*)d_in[5];
    float*       out       = (float*)d_out;

    offsets_kernel<<<(NB + 1 + 255) / 256, 256>>>(seg);
    embh_kernel<<<MPAD, 160>>>(emb);
    wcath_kernel<<<NPADC, 160>>>(W1);
    rowsum_kernel<<<75, 256>>>(W1);
    dim3 ggrid(NPADC / BN, MPAD / BM);   // (10, 228), x-fast shares A via L2
    proj_gemm_kernel<<<ggrid, 128>>>();
    agg_kernel<<<NB, AGG_T>>>(nodes, neighbors, b1, out);
}